// round 8
// baseline (speedup 1.0000x reference)
#include <cuda_runtime.h>
#include <cuda_bf16.h>
#include <math.h>
#include <stdint.h>
#include <stddef.h>

#define BATCH 4
#define SEQ 1024
#define DMODEL 1024
#define NH 16
#define HD 64
#define NROWS (BATCH*SEQ)          // 4096

#define PITCH 40                   // bf16 row pitch for 32-wide K tiles (proj)
#define SZB (128*PITCH*2)          // bytes per 128x32 bf16 sub-tile (10240)
#define PROJ_SMEM (8*SZB)          // 2 buffers x (Ah,Al,Bh,Bl) = 81920

// Fused attention smem layout (dynamic)
#define PP 1032                    // P row pitch (bf16 elements)
#define PT 72                      // K/V/Q tile row pitch (bf16 elements)
#define OFF_PH 0
#define OFF_PL (OFF_PH + 32*PP*2)          // 66048
#define OFF_TH (OFF_PL + 32*PP*2)          // 132096
#define OFF_TL (OFF_TH + 128*PT*2)         // 150528
#define OFF_QH (OFF_TL + 128*PT*2)         // 168960
#define OFF_QL (OFF_QH + 32*PT*2)          // 173568
#define OFF_RED (OFF_QL + 32*PT*2)         // 178176
#define OFF_INV (OFF_RED + 512)            // 178688
#define ATT_SMEM (OFF_INV + 128)           // 178816

// Scratch (static device globals: allowed; no runtime allocation)
__device__ float g_qp[NROWS*DMODEL];
__device__ float g_kp[NROWS*DMODEL];
__device__ float g_vp[NROWS*DMODEL];
__device__ float g_ctx[NROWS*DMODEL];

// ---------------------------------------------------------------------------
// Baseline-ISA tensor-core helpers
// ---------------------------------------------------------------------------
__device__ __forceinline__ uint32_t cvta_s(const void* p) {
    return (uint32_t)__cvta_generic_to_shared(p);
}

__device__ __forceinline__ void ldsm4(uint32_t* r, uint32_t addr) {
    asm volatile("ldmatrix.sync.aligned.m8n8.x4.shared.b16 {%0,%1,%2,%3}, [%4];"
                 : "=r"(r[0]), "=r"(r[1]), "=r"(r[2]), "=r"(r[3]) : "r"(addr));
}

__device__ __forceinline__ void ldsm4t(uint32_t* r, uint32_t addr) {
    asm volatile("ldmatrix.sync.aligned.m8n8.x4.trans.shared.b16 {%0,%1,%2,%3}, [%4];"
                 : "=r"(r[0]), "=r"(r[1]), "=r"(r[2]), "=r"(r[3]) : "r"(addr));
}

__device__ __forceinline__ void mma_bf16(float* c, const uint32_t* a, const uint32_t* b) {
    asm volatile(
        "mma.sync.aligned.m16n8k16.row.col.f32.bf16.bf16.f32 "
        "{%0,%1,%2,%3}, {%4,%5,%6,%7}, {%8,%9}, {%0,%1,%2,%3};"
        : "+f"(c[0]), "+f"(c[1]), "+f"(c[2]), "+f"(c[3])
        : "r"(a[0]), "r"(a[1]), "r"(a[2]), "r"(a[3]), "r"(b[0]), "r"(b[1]));
}

__device__ __forceinline__ void split2(float x, float y, uint32_t& hi, uint32_t& lo) {
    __nv_bfloat162 h = __floats2bfloat162_rn(x, y);
    float hx = __bfloat162float(h.x);
    float hy = __bfloat162float(h.y);
    __nv_bfloat162 l = __floats2bfloat162_rn(x - hx, y - hy);
    hi = *reinterpret_cast<uint32_t*>(&h);
    lo = *reinterpret_cast<uint32_t*>(&l);
}

__device__ __forceinline__ float2 unpack2(uint32_t hi, uint32_t lo) {
    __nv_bfloat162 h = *reinterpret_cast<__nv_bfloat162*>(&hi);
    __nv_bfloat162 l = *reinterpret_cast<__nv_bfloat162*>(&lo);
    return make_float2(__bfloat162float(h.x) + __bfloat162float(l.x),
                       __bfloat162float(h.y) + __bfloat162float(l.y));
}

__device__ __forceinline__ void sts2(uint32_t addr, uint32_t a, uint32_t b) {
    asm volatile("st.shared.v2.b32 [%0], {%1,%2};" :: "r"(addr), "r"(a), "r"(b) : "memory");
}

// split + store one 128x32 fp32 tile (4 float4 regs) to hi/lo smem (proj)
__device__ __forceinline__ void store_tile(uint32_t uh, uint32_t ul,
                                           const float4* v, int rg, int ck) {
#pragma unroll
    for (int i = 0; i < 4; i++) {
        int off2 = ((rg + 32 * i) * PITCH + ck * 4) * 2;
        uint32_t h0, l0, h1, l1;
        split2(v[i].x, v[i].y, h0, l0);
        split2(v[i].z, v[i].w, h1, l1);
        sts2(uh + off2, h0, h1);
        sts2(ul + off2, l0, l1);
    }
}

// ---------------------------------------------------------------------------
// Projections, double-buffered pipeline
// ---------------------------------------------------------------------------
__global__ void __launch_bounds__(256, 1) proj_mma_kernel(
    const float* __restrict__ q, const float* __restrict__ k, const float* __restrict__ v,
    const float* __restrict__ Wq, const float* __restrict__ bq,
    const float* __restrict__ Wk, const float* __restrict__ bk,
    const float* __restrict__ Wv, const float* __restrict__ bv)
{
    extern __shared__ __align__(16) char dynsm[];

    const float *X, *W, *bias; float* O;
    if (blockIdx.z == 0)      { X = q; W = Wq; bias = bq; O = g_qp; }
    else if (blockIdx.z == 1) { X = k; W = Wk; bias = bk; O = g_kp; }
    else                      { X = v; W = Wv; bias = bv; O = g_vp; }

    const int tid = threadIdx.x;
    const int w = tid >> 5, ln = tid & 31;
    const int wm = (w >> 2) * 64;
    const int wn = (w & 3) * 32;
    const int rg = tid >> 3;
    const int ck = tid & 7;
    const int row0 = blockIdx.y * 128, col0 = blockIdx.x * 128;

    const float* Ab = X + (size_t)(row0 + rg) * DMODEL + ck * 4;
    const float* Bb = W + (size_t)(col0 + rg) * DMODEL + ck * 4;

    const uint32_t sb = cvta_s(dynsm);

    float acc[4][4][4];
#pragma unroll
    for (int i = 0; i < 4; i++)
#pragma unroll
        for (int j = 0; j < 4; j++)
#pragma unroll
            for (int t = 0; t < 4; t++) acc[i][j][t] = 0.f;

    float4 ar[4], br[4];
#pragma unroll
    for (int i = 0; i < 4; i++) {
        ar[i] = *(const float4*)(Ab + (size_t)i * 32 * DMODEL);
        br[i] = *(const float4*)(Bb + (size_t)i * 32 * DMODEL);
    }
    store_tile(sb,           sb + SZB,     ar, rg, ck);
    store_tile(sb + 2 * SZB, sb + 3 * SZB, br, rg, ck);
    __syncthreads();

    const int NST = DMODEL / 32;
    for (int s = 0; s < NST; s++) {
        const uint32_t bc = sb + (uint32_t)(s & 1) * 4 * SZB;

        if (s + 1 < NST) {
            const float* An = Ab + (size_t)(s + 1) * 32;
            const float* Bn = Bb + (size_t)(s + 1) * 32;
#pragma unroll
            for (int i = 0; i < 4; i++) {
                ar[i] = *(const float4*)(An + (size_t)i * 32 * DMODEL);
                br[i] = *(const float4*)(Bn + (size_t)i * 32 * DMODEL);
            }
        }

#pragma unroll
        for (int ks = 0; ks < 2; ks++) {
            uint32_t ah[4][4], al[4][4], bh[2][4], bl[2][4];
#pragma unroll
            for (int i = 0; i < 4; i++) {
                uint32_t off = (uint32_t)((wm + i * 16 + (ln & 15)) * PITCH) * 2
                             + (uint32_t)ks * 32 + (uint32_t)(ln >> 4) * 16;
                ldsm4(ah[i], bc + off);
                ldsm4(al[i], bc + SZB + off);
            }
#pragma unroll
            for (int g = 0; g < 2; g++) {
                uint32_t row = (uint32_t)(wn + g * 16 + ((ln >> 4) << 3) + (ln & 7));
                uint32_t off = row * PITCH * 2 + (uint32_t)ks * 32
                             + (uint32_t)((ln >> 3) & 1) * 16;
                ldsm4(bh[g], bc + 2 * SZB + off);
                ldsm4(bl[g], bc + 3 * SZB + off);
            }
#pragma unroll
            for (int i = 0; i < 4; i++)
#pragma unroll
                for (int j = 0; j < 4; j++) {
                    const uint32_t* bhj = &bh[j >> 1][(j & 1) * 2];
                    const uint32_t* blj = &bl[j >> 1][(j & 1) * 2];
                    mma_bf16(acc[i][j], ah[i], bhj);
                    mma_bf16(acc[i][j], ah[i], blj);
                    mma_bf16(acc[i][j], al[i], bhj);
                }
        }

        if (s + 1 < NST) {
            const uint32_t bn = sb + (uint32_t)((s + 1) & 1) * 4 * SZB;
            store_tile(bn,           bn + SZB,     ar, rg, ck);
            store_tile(bn + 2 * SZB, bn + 3 * SZB, br, rg, ck);
        }
        __syncthreads();
    }

#pragma unroll
    for (int i = 0; i < 4; i++) {
        int r = row0 + wm + i * 16 + (ln >> 2);
#pragma unroll
        for (int j = 0; j < 4; j++) {
            int c = col0 + wn + j * 8 + 2 * (ln & 3);
            float b0 = bias[c], b1 = bias[c + 1];
            *(float2*)&O[(size_t)r * DMODEL + c] =
                make_float2(acc[i][j][0] + b0, acc[i][j][1] + b1);
            *(float2*)&O[(size_t)(r + 8) * DMODEL + c] =
                make_float2(acc[i][j][2] + b0, acc[i][j][3] + b1);
        }
    }
}

// ---------------------------------------------------------------------------
// Fused attention: one CTA = (head z, 32 q-rows). P kept in SMEM (bf16 hi/lo).
// Phase 1: S = Q@K^T tile-by-tile -> exp -> sP, rowsums.
// Phase 2: normalized att write (once) + ctx = P@V, normalized at epilogue.
// ---------------------------------------------------------------------------
__global__ void __launch_bounds__(256, 1) attn_fused_kernel(
    float* __restrict__ att, const unsigned char* __restrict__ masks)
{
    extern __shared__ __align__(16) char dynsm[];
    const uint32_t sb = cvta_s(dynsm);
    const uint32_t uPh = sb + OFF_PH, uPl = sb + OFF_PL;
    const uint32_t uTh = sb + OFF_TH, uTl = sb + OFF_TL;
    const uint32_t uQh = sb + OFF_QH, uQl = sb + OFF_QL;
    float* sred = reinterpret_cast<float*>(dynsm + OFF_RED);
    float* sinv = reinterpret_cast<float*>(dynsm + OFF_INV);

    const int z = blockIdx.y;              // b*16 + h
    const int b = z >> 4, h = z & 15;
    const int q0 = blockIdx.x * 32;

    const int tid = threadIdx.x;
    const int w = tid >> 5, ln = tid & 31;
    const int wm = (w >> 2) * 16;          // phase-1/2 warp m-offset (0/16)
    const int nb = (w & 3) * 32;           // phase-1 n-slice / phase-2 k-slice
    const int r_lo = wm + (ln >> 2);
    const int i0 = q0 + r_lo;

    const int trow = tid >> 4, tc = tid & 15;   // 128x64 tile loader

    // ---- load Q block (32 x 64) ----
#pragma unroll
    for (int i = 0; i < 2; i++) {
        int r = trow + 16 * i;
        float4 v4 = *(const float4*)&g_qp[((size_t)b * SEQ + q0 + r) * DMODEL + h * HD + tc * 4];
        uint32_t h0, l0, h1, l1;
        split2(v4.x, v4.y, h0, l0);
        split2(v4.z, v4.w, h1, l1);
        int off2 = (r * PT + tc * 4) * 2;
        sts2(uQh + off2, h0, h1);
        sts2(uQl + off2, l0, l1);
    }
    __syncthreads();

    uint32_t aqh[4][4], aql[4][4];
#pragma unroll
    for (int ks = 0; ks < 4; ks++) {
        uint32_t off = (uint32_t)((wm + (ln & 15)) * PT) * 2
                     + (uint32_t)ks * 32 + (uint32_t)(ln >> 4) * 16;
        ldsm4(aqh[ks], uQh + off);
        ldsm4(aql[ks], uQl + off);
    }

    float rs0 = 0.f, rs1 = 0.f;

    // prefetch K tile 0
    float4 kr[8];
#pragma unroll
    for (int i = 0; i < 8; i++)
        kr[i] = *(const float4*)&g_kp[((size_t)b * SEQ + trow + 16 * i) * DMODEL + h * HD + tc * 4];

    // ================= Phase 1 =================
    for (int nt = 0; nt < 8; nt++) {
        __syncthreads();
#pragma unroll
        for (int i = 0; i < 8; i++) {
            int r = trow + 16 * i;
            uint32_t h0, l0, h1, l1;
            split2(kr[i].x, kr[i].y, h0, l0);
            split2(kr[i].z, kr[i].w, h1, l1);
            int off2 = (r * PT + tc * 4) * 2;
            sts2(uTh + off2, h0, h1);
            sts2(uTl + off2, l0, l1);
        }
        __syncthreads();

        if (nt + 1 < 8) {
#pragma unroll
            for (int i = 0; i < 8; i++)
                kr[i] = *(const float4*)&g_kp[((size_t)b * SEQ + (nt + 1) * 128 + trow + 16 * i) * DMODEL + h * HD + tc * 4];
        }

        float s[4][4];
#pragma unroll
        for (int j = 0; j < 4; j++)
#pragma unroll
            for (int t = 0; t < 4; t++) s[j][t] = 0.f;

#pragma unroll
        for (int ks = 0; ks < 4; ks++) {
            uint32_t bh[2][4], bl[2][4];
#pragma unroll
            for (int g = 0; g < 2; g++) {
                uint32_t row = (uint32_t)(nb + g * 16 + ((ln >> 4) << 3) + (ln & 7));
                uint32_t off = row * PT * 2 + (uint32_t)ks * 32
                             + (uint32_t)((ln >> 3) & 1) * 16;
                ldsm4(bh[g], uTh + off);
                ldsm4(bl[g], uTl + off);
            }
#pragma unroll
            for (int j = 0; j < 4; j++) {
                const uint32_t* bhj = &bh[j >> 1][(j & 1) * 2];
                const uint32_t* blj = &bl[j >> 1][(j & 1) * 2];
                mma_bf16(s[j], aqh[ks], bhj);
                mma_bf16(s[j], aqh[ks], blj);
                mma_bf16(s[j], aql[ks], bhj);
            }
        }

        // mask + exp + store P to smem
#pragma unroll
        for (int j = 0; j < 4; j++) {
            int col = nt * 128 + nb + j * 8 + 2 * (ln & 3);
            const unsigned char* mp = masks + ((size_t)b * SEQ + i0) * SEQ + col;
            uchar2 ma = *(const uchar2*)mp;
            uchar2 mb = *(const uchar2*)(mp + 8 * SEQ);
            float e00 = ma.x ? 0.f : __expf(0.125f * s[j][0]);
            float e01 = ma.y ? 0.f : __expf(0.125f * s[j][1]);
            float e10 = mb.x ? 0.f : __expf(0.125f * s[j][2]);
            float e11 = mb.y ? 0.f : __expf(0.125f * s[j][3]);
            rs0 += e00 + e01;
            rs1 += e10 + e11;
            uint32_t h0, l0, h1, l1;
            split2(e00, e01, h0, l0);
            split2(e10, e11, h1, l1);
            uint32_t a0 = uPh + (uint32_t)(r_lo * PP + col) * 2;
            uint32_t a1 = uPh + (uint32_t)((r_lo + 8) * PP + col) * 2;
            asm volatile("st.shared.b32 [%0], %1;" :: "r"(a0), "r"(h0) : "memory");
            asm volatile("st.shared.b32 [%0], %1;" :: "r"(a1), "r"(h1) : "memory");
            a0 = uPl + (uint32_t)(r_lo * PP + col) * 2;
            a1 = uPl + (uint32_t)((r_lo + 8) * PP + col) * 2;
            asm volatile("st.shared.b32 [%0], %1;" :: "r"(a0), "r"(l0) : "memory");
            asm volatile("st.shared.b32 [%0], %1;" :: "r"(a1), "r"(l1) : "memory");
        }
    }

    // prefetch V tile 0 (overlap with reduction)
    float4 vr8[8];
#pragma unroll
    for (int i = 0; i < 8; i++)
        vr8[i] = *(const float4*)&g_vp[((size_t)b * SEQ + trow + 16 * i) * DMODEL + h * HD + tc * 4];

    // ================= rowsum -> inv =================
    rs0 += __shfl_xor_sync(0xffffffffu, rs0, 1);
    rs0 += __shfl_xor_sync(0xffffffffu, rs0, 2);
    rs1 += __shfl_xor_sync(0xffffffffu, rs1, 1);
    rs1 += __shfl_xor_sync(0xffffffffu, rs1, 2);
    if ((ln & 3) == 0) {
        sred[(w & 3) * 32 + r_lo]     = rs0;
        sred[(w & 3) * 32 + r_lo + 8] = rs1;
    }
    __syncthreads();
    if (tid < 32)
        sinv[tid] = 1.f / (sred[tid] + sred[32 + tid] + sred[64 + tid] + sred[96 + tid]);

    float ctx[8][4];
#pragma unroll
    for (int j = 0; j < 8; j++)
#pragma unroll
        for (int t = 0; t < 4; t++) ctx[j][t] = 0.f;

    const int arow = tid >> 3;                 // att-writer row (0..31)
    const int acb = (tid & 7) * 16;            // att-writer col base within 128

    // ================= Phase 2 =================
    for (int nt = 0; nt < 8; nt++) {
        __syncthreads();
#pragma unroll
        for (int i = 0; i < 8; i++) {
            int r = trow + 16 * i;
            uint32_t h0, l0, h1, l1;
            split2(vr8[i].x, vr8[i].y, h0, l0);
            split2(vr8[i].z, vr8[i].w, h1, l1);
            int off2 = (r * PT + tc * 4) * 2;
            sts2(uTh + off2, h0, h1);
            sts2(uTl + off2, l0, l1);
        }
        __syncthreads();

        if (nt + 1 < 8) {
#pragma unroll
            for (int i = 0; i < 8; i++)
                vr8[i] = *(const float4*)&g_vp[((size_t)b * SEQ + (nt + 1) * 128 + trow + 16 * i) * DMODEL + h * HD + tc * 4];
        }

        // normalized att write for this 128-col stripe
        {
            const float inv = sinv[arow];
            float* dst = &att[((size_t)z * SEQ + q0 + arow) * SEQ + nt * 128 + acb];
            const uint32_t pbase = (uint32_t)(arow * PP + nt * 128 + acb) * 2;
#pragma unroll
            for (int c4 = 0; c4 < 4; c4++) {
                uint32_t h0 = *reinterpret_cast<uint32_t*>(dynsm + OFF_PH + pbase + c4 * 8);
                uint32_t h1 = *reinterpret_cast<uint32_t*>(dynsm + OFF_PH + pbase + c4 * 8 + 4);
                uint32_t l0 = *reinterpret_cast<uint32_t*>(dynsm + OFF_PL + pbase + c4 * 8);
                uint32_t l1 = *reinterpret_cast<uint32_t*>(dynsm + OFF_PL + pbase + c4 * 8 + 4);
                float2 p0 = unpack2(h0, l0);
                float2 p1 = unpack2(h1, l1);
                float4 o = make_float4(p0.x * inv, p0.y * inv, p1.x * inv, p1.y * inv);
                *(float4*)(dst + c4 * 4) = o;
            }
        }

        // ctx += P[:, nt*128 + ksl : +32] @ V[ksl : +32, :]
#pragma unroll
        for (int kc = 0; kc < 2; kc++) {
            uint32_t aph[4], apl[4], bh[4][4], bl[4][4];
            {
                uint32_t off = (uint32_t)((wm + (ln & 15)) * PP) * 2
                             + (uint32_t)(nt * 128 + nb + kc * 16) * 2
                             + (uint32_t)(ln >> 4) * 16;
                ldsm4(aph, uPh + off);
                ldsm4(apl, uPl + off);
            }
#pragma unroll
            for (int g = 0; g < 4; g++) {
                uint32_t rk = (uint32_t)(nb + kc * 16 + (((ln >> 3) & 1) << 3) + (ln & 7));
                uint32_t nc = (uint32_t)(g * 16 + ((ln >> 4) << 3));
                uint32_t off = rk * PT * 2 + nc * 2;
                ldsm4t(bh[g], uTh + off);
                ldsm4t(bl[g], uTl + off);
            }
#pragma unroll
            for (int j = 0; j < 8; j++) {
                const uint32_t* bhj = &bh[j >> 1][(j & 1) * 2];
                const uint32_t* blj = &bl[j >> 1][(j & 1) * 2];
                mma_bf16(ctx[j], aph, bhj);
                mma_bf16(ctx[j], aph, blj);
                mma_bf16(ctx[j], apl, bhj);
            }
        }
    }

    // ================= cross-warp ctx k-reduce =================
    float* sctx = reinterpret_cast<float*>(dynsm + OFF_TH);   // 32x64 fp32 = 8KB
    __syncthreads();
#pragma unroll
    for (int c = 0; c < 4; c++) {
        if ((w & 3) == c) {
#pragma unroll
            for (int j = 0; j < 8; j++) {
                int col = j * 8 + 2 * (ln & 3);
                int o0 = r_lo * 64 + col;
                int o1 = (r_lo + 8) * 64 + col;
                if (c == 0) {
                    sctx[o0] = ctx[j][0]; sctx[o0 + 1] = ctx[j][1];
                    sctx[o1] = ctx[j][2]; sctx[o1 + 1] = ctx[j][3];
                } else {
                    sctx[o0] += ctx[j][0]; sctx[o0 + 1] += ctx[j][1];
                    sctx[o1] += ctx[j][2]; sctx[o1 + 1] += ctx[j][3];
                }
            }
        }
        __syncthreads();
    }

    // write normalized ctx
    {
        int row = tid >> 3, cb = (tid & 7) * 8;
        float inv = sinv[row];
        float* dst = &g_ctx[((size_t)b * SEQ + q0 + row) * DMODEL + h * HD + cb];
#pragma unroll
        for (int c = 0; c < 8; c++) dst[c] = sctx[row * 64 + cb + c] * inv;
    }
}

// ---------------------------------------------------------------------------
// output = LayerNorm(qp + ctx) * g + b
// ---------------------------------------------------------------------------
__global__ void ln_kernel(float* __restrict__ out,
                          const float* __restrict__ gam,
                          const float* __restrict__ bet)
{
    __shared__ float reds[8];
    __shared__ float redq[8];
    __shared__ float stat[2];

    int row = blockIdx.x;
    const float* xq = g_qp + (size_t)row * DMODEL;
    const float* xc = g_ctx + (size_t)row * DMODEL;
    int j = threadIdx.x * 4;

    float4 a = *(const float4*)(xq + j);
    float4 c = *(const float4*)(xc + j);
    float x0 = a.x + c.x, x1 = a.y + c.y, x2 = a.z + c.z, x3 = a.w + c.w;

    float s = x0 + x1 + x2 + x3;
    float sq = x0 * x0 + x1 * x1 + x2 * x2 + x3 * x3;
#pragma unroll
    for (int o = 16; o; o >>= 1) {
        s += __shfl_xor_sync(0xffffffffu, s, o);
        sq += __shfl_xor_sync(0xffffffffu, sq, o);
    }
    if ((threadIdx.x & 31) == 0) { reds[threadIdx.x >> 5] = s; redq[threadIdx.x >> 5] = sq; }
    __syncthreads();
    if (threadIdx.x == 0) {
        float S = 0.f, Q = 0.f;
#pragma unroll
        for (int w = 0; w < 8; w++) { S += reds[w]; Q += redq[w]; }
        float mu = S * (1.0f / DMODEL);
        float var = Q * (1.0f / DMODEL) - mu * mu;
        stat[0] = mu;
        stat[1] = rsqrtf(var + 1e-6f);
    }
    __syncthreads();
    float mu = stat[0], r = stat[1];

    float4 g4 = *(const float4*)(gam + j);
    float4 b4 = *(const float4*)(bet + j);
    float4 o4;
    o4.x = (x0 - mu) * r * g4.x + b4.x;
    o4.y = (x1 - mu) * r * g4.y + b4.y;
    o4.z = (x2 - mu) * r * g4.z + b4.z;
    o4.w = (x3 - mu) * r * g4.w + b4.w;
    *(float4*)(out + (size_t)row * DMODEL + j) = o4;
}

// ---------------------------------------------------------------------------
extern "C" void kernel_launch(void* const* d_in, const int* in_sizes, int n_in,
                              void* d_out, int out_size)
{
    const float* q  = (const float*)d_in[0];
    const float* k  = (const float*)d_in[1];
    const float* v  = (const float*)d_in[2];
    const unsigned char* masks = (const unsigned char*)d_in[3];
    const float* Wq = (const float*)d_in[4];
    const float* bq = (const float*)d_in[5];
    const float* Wk = (const float*)d_in[6];
    const float* bk = (const float*)d_in[7];
    const float* Wv = (const float*)d_in[8];
    const float* bv = (const float*)d_in[9];
    const float* lng = (const float*)d_in[10];
    const float* lnb = (const float*)d_in[11];

    float* out = (float*)d_out;
    float* att = out + (size_t)BATCH * SEQ * DMODEL;

    cudaFuncSetAttribute(proj_mma_kernel,
                         cudaFuncAttributeMaxDynamicSharedMemorySize, PROJ_SMEM);
    cudaFuncSetAttribute(attn_fused_kernel,
                         cudaFuncAttributeMaxDynamicSharedMemorySize, ATT_SMEM);

    proj_mma_kernel<<<dim3(DMODEL / 128, NROWS / 128, 3), 256, PROJ_SMEM>>>(
        q, k, v, Wq, bq, Wk, bk, Wv, bv);
    attn_fused_kernel<<<dim3(SEQ / 32, BATCH * NH), 256, ATT_SMEM>>>(att, masks);
    ln_kernel<<<NROWS, 256>>>(out, lng, lnb);
}